// round 15
// baseline (speedup 1.0000x reference)
#include <cuda_runtime.h>
#include <cuda_fp16.h>

#define N_NODES_MAX 100000
#define IN_CH 256
#define QK_GRID 740            // 148 SMs * 5 blocks (regs ~48)
#define GRID6 888              // 148 SMs * 6 blocks
#define EMB_BLOCKS 32          // last 32 pool blocks do the final matvec
#define LOG2E 1.4426950408889634f

__device__ float  g_q[N_NODES_MAX];
__device__ float  g_k[N_NODES_MAX];          // stores k * log2(e)
__device__ float  g_aw[N_NODES_MAX];
__device__ float  g_sum;
__device__ float  g_s[IN_CH];
__device__ int    g_counter;
// fp16 side-copy of x: 100000*256*2B = 51.2 MB — small enough to stay L2-hot
// between qk (writer) and pool (reader).
__device__ __half g_x16[(size_t)N_NODES_MAX * IN_CH];

__device__ __forceinline__ unsigned h2_as_u32(__half2 h) {
    return *reinterpret_cast<unsigned*>(&h);
}
__device__ __forceinline__ __half2 u32_as_h2(unsigned u) {
    return *reinterpret_cast<__half2*>(&u);
}

// ---------------------------------------------------------------------------
// Kernel 1: init + q[n] = x[n]·Wq + bq, k[n] = (x[n]·Wk + bk)·log2e,
// AND write fp16 copy of x. x read with __ldcs (read-once streaming — the
// fp32 x is never touched again; keeps L2 free for the fp16 copy).
// ---------------------------------------------------------------------------
__global__ void __launch_bounds__(256)
qk_kernel(const float* __restrict__ x,
          const float* __restrict__ Wq, const float* __restrict__ bq,
          const float* __restrict__ Wk, const float* __restrict__ bk,
          float* __restrict__ out,          // zero out[0:256] for emb atomics
          int n_nodes) {
    int tid     = blockIdx.x * blockDim.x + threadIdx.x;
    int nthread = gridDim.x * blockDim.x;

    if (tid < n_nodes) g_aw[tid] = 0.0f;
    if (tid < IN_CH)  { g_s[tid] = 0.0f; out[tid] = 0.0f; }
    if (tid == 0)     { g_sum = 0.0f; g_counter = 0; }

    int lane   = threadIdx.x & 31;
    int warp   = tid >> 5;
    int nwarps = nthread >> 5;

    const float4* wq4 = reinterpret_cast<const float4*>(Wq);
    const float4* wk4 = reinterpret_cast<const float4*>(Wk);
    // lane owns channels [8*lane, 8*lane+8)
    float4 q0 = wq4[2 * lane], q1 = wq4[2 * lane + 1];
    float4 k0 = wk4[2 * lane], k1 = wk4[2 * lane + 1];
    float bqv = bq[0], bkv = bk[0];

    int n = warp;
    for (; n + 3 * nwarps < n_nodes; n += 4 * nwarps) {
        float dq[4], dk[4];
        #pragma unroll
        for (int u = 0; u < 4; u++) {
            int nu = n + u * nwarps;
            const float4* xr = reinterpret_cast<const float4*>(
                x + (size_t)nu * IN_CH);
            float4 a = __ldcs(&xr[2 * lane]);
            float4 b = __ldcs(&xr[2 * lane + 1]);
            dq[u] = a.x*q0.x + a.y*q0.y + a.z*q0.z + a.w*q0.w
                  + b.x*q1.x + b.y*q1.y + b.z*q1.z + b.w*q1.w;
            dk[u] = a.x*k0.x + a.y*k0.y + a.z*k0.z + a.w*k0.w
                  + b.x*k1.x + b.y*k1.y + b.z*k1.z + b.w*k1.w;
            // fp16 copy: 8 halves = 16 B = one uint4 store per lane
            uint4 pk;
            pk.x = h2_as_u32(__floats2half2_rn(a.x, a.y));
            pk.y = h2_as_u32(__floats2half2_rn(a.z, a.w));
            pk.z = h2_as_u32(__floats2half2_rn(b.x, b.y));
            pk.w = h2_as_u32(__floats2half2_rn(b.z, b.w));
            reinterpret_cast<uint4*>(g_x16 + (size_t)nu * IN_CH)[lane] = pk;
        }
        #pragma unroll
        for (int o = 16; o > 0; o >>= 1) {
            #pragma unroll
            for (int u = 0; u < 4; u++) {
                dq[u] += __shfl_xor_sync(0xffffffffu, dq[u], o);
                dk[u] += __shfl_xor_sync(0xffffffffu, dk[u], o);
            }
        }
        if (lane == 0) {
            #pragma unroll
            for (int u = 0; u < 4; u++) {
                g_q[n + u * nwarps] = dq[u] + bqv;
                g_k[n + u * nwarps] = (dk[u] + bkv) * LOG2E;
            }
        }
    }
    for (; n < n_nodes; n += nwarps) {
        const float4* xr = reinterpret_cast<const float4*>(x + (size_t)n * IN_CH);
        float4 a = __ldcs(&xr[2 * lane]);
        float4 b = __ldcs(&xr[2 * lane + 1]);
        float dq = a.x*q0.x + a.y*q0.y + a.z*q0.z + a.w*q0.w
                 + b.x*q1.x + b.y*q1.y + b.z*q1.z + b.w*q1.w;
        float dk = a.x*k0.x + a.y*k0.y + a.z*k0.z + a.w*k0.w
                 + b.x*k1.x + b.y*k1.y + b.z*k1.z + b.w*k1.w;
        uint4 pk;
        pk.x = h2_as_u32(__floats2half2_rn(a.x, a.y));
        pk.y = h2_as_u32(__floats2half2_rn(a.z, a.w));
        pk.z = h2_as_u32(__floats2half2_rn(b.x, b.y));
        pk.w = h2_as_u32(__floats2half2_rn(b.z, b.w));
        reinterpret_cast<uint4*>(g_x16 + (size_t)n * IN_CH)[lane] = pk;
        #pragma unroll
        for (int o = 16; o > 0; o >>= 1) {
            dq += __shfl_xor_sync(0xffffffffu, dq, o);
            dk += __shfl_xor_sync(0xffffffffu, dk, o);
        }
        if (lane == 0) { g_q[n] = dq + bqv; g_k[n] = (dk + bkv) * LOG2E; }
    }
}

// ---------------------------------------------------------------------------
// Kernel 2 (R8 winner, unchanged): edge pass, 8 edges/iter, in-loop sum.
// Index loads __ldcs (don't evict the fp16 x copy). Prefetches Wv+bv.
// ---------------------------------------------------------------------------
__global__ void __launch_bounds__(256, 6)
edge_kernel(const int* __restrict__ row,
            const int* __restrict__ col,
            const float* __restrict__ Wv,
            const float* __restrict__ bv,
            int n_edges) {
    if (blockIdx.x < 64) {
        const float4* wv4 = reinterpret_cast<const float4*>(Wv);
        float4 p = __ldcg(&wv4[blockIdx.x * 256 + threadIdx.x]);
        float t = p.x + p.y + p.z + p.w;
        if (blockIdx.x == 0 && threadIdx.x < 64)
            t += __ldcg(&bv[threadIdx.x * 4]);
        if (t != t) atomicAdd(&g_sum, t);   // never true (no NaNs) — defeats DCE
    }

    int tid    = blockIdx.x * blockDim.x + threadIdx.x;
    int stride = gridDim.x * blockDim.x;
    int noct   = n_edges >> 3;

    const int4* row4 = reinterpret_cast<const int4*>(row);
    const int4* col4 = reinterpret_cast<const int4*>(col);

    float local = 0.0f;
    for (int i = tid; i < noct; i += stride) {
        int4 r0 = __ldcs(&row4[2 * i]), r1 = __ldcs(&row4[2 * i + 1]);
        int4 c0 = __ldcs(&col4[2 * i]), c1 = __ldcs(&col4[2 * i + 1]);

        float q0 = g_q[r0.x], q1 = g_q[r0.y], q2 = g_q[r0.z], q3 = g_q[r0.w];
        float q4 = g_q[r1.x], q5 = g_q[r1.y], q6 = g_q[r1.z], q7 = g_q[r1.w];
        float k0 = g_k[c0.x], k1 = g_k[c0.y], k2 = g_k[c0.z], k3 = g_k[c0.w];
        float k4 = g_k[c1.x], k5 = g_k[c1.y], k6 = g_k[c1.z], k7 = g_k[c1.w];

        float a0 = q0*k0, a1 = q1*k1, a2 = q2*k2, a3 = q3*k3;
        float a4 = q4*k4, a5 = q5*k5, a6 = q6*k6, a7 = q7*k7;
        a0 = fmaxf(a0, 0.2f*a0);  a1 = fmaxf(a1, 0.2f*a1);
        a2 = fmaxf(a2, 0.2f*a2);  a3 = fmaxf(a3, 0.2f*a3);
        a4 = fmaxf(a4, 0.2f*a4);  a5 = fmaxf(a5, 0.2f*a5);
        a6 = fmaxf(a6, 0.2f*a6);  a7 = fmaxf(a7, 0.2f*a7);
        float e0 = exp2f(a0), e1 = exp2f(a1), e2 = exp2f(a2), e3 = exp2f(a3);
        float e4 = exp2f(a4), e5 = exp2f(a5), e6 = exp2f(a6), e7 = exp2f(a7);

        atomicAdd(&g_aw[r0.x], e0);
        atomicAdd(&g_aw[r0.y], e1);
        atomicAdd(&g_aw[r0.z], e2);
        atomicAdd(&g_aw[r0.w], e3);
        atomicAdd(&g_aw[r1.x], e4);
        atomicAdd(&g_aw[r1.y], e5);
        atomicAdd(&g_aw[r1.z], e6);
        atomicAdd(&g_aw[r1.w], e7);
        local += ((e0 + e1) + (e2 + e3)) + ((e4 + e5) + (e6 + e7));
    }
    for (int e = (noct << 3) + tid; e < n_edges; e += stride) {
        float a = g_q[row[e]] * g_k[col[e]];
        a = fmaxf(a, 0.2f * a);
        float ex = exp2f(a);
        atomicAdd(&g_aw[row[e]], ex);
        local += ex;
    }

    __shared__ float sh[32];
    #pragma unroll
    for (int o = 16; o > 0; o >>= 1) local += __shfl_xor_sync(0xffffffffu, local, o);
    if ((threadIdx.x & 31) == 0) sh[threadIdx.x >> 5] = local;
    __syncthreads();
    if (threadIdx.x < 32) {
        float v = (threadIdx.x < (blockDim.x >> 5)) ? sh[threadIdx.x] : 0.0f;
        #pragma unroll
        for (int o = 16; o > 0; o >>= 1) v += __shfl_xor_sync(0xffffffffu, v, o);
        if (threadIdx.x == 0) atomicAdd(&g_sum, v);
    }
}

// ---------------------------------------------------------------------------
// Kernel 3: normalize aw + s = sum_n aw_norm[n]*x16[n], FUSED final matvec.
// Reads the fp16 copy (51 MB, mostly L2-hot): thread owns an 8-channel slot
// (one uint4 = 8 halves per node), 4x node unroll.
// ---------------------------------------------------------------------------
__global__ void __launch_bounds__(256, 6)
pool_kernel(const float* __restrict__ Wv,
            const float* __restrict__ bv,
            float* __restrict__ graph_emb,
            float* __restrict__ aw_out,
            int n_nodes) {
    float inv = 1.0f / g_sum;
    int tid     = blockIdx.x * blockDim.x + threadIdx.x;
    int slot    = tid & 31;                  // 8-channel slot: ch [8*slot, 8*slot+8)
    int n0      = tid >> 5;
    int nstride = (gridDim.x * blockDim.x) >> 5;

    float acc[8];
    #pragma unroll
    for (int j = 0; j < 8; j++) acc[j] = 0.0f;

    const uint4* x16v = reinterpret_cast<const uint4*>(g_x16);   // 32 uint4 per row

    int n = n0;
    for (; n + 3 * nstride < n_nodes; n += 4 * nstride) {
        int na = n, nb = n + nstride, nc = n + 2 * nstride, nd = n + 3 * nstride;
        float w0 = g_aw[na] * inv;
        float w1 = g_aw[nb] * inv;
        float w2 = g_aw[nc] * inv;
        float w3 = g_aw[nd] * inv;
        uint4 p0 = x16v[(size_t)na * 32 + slot];
        uint4 p1 = x16v[(size_t)nb * 32 + slot];
        uint4 p2 = x16v[(size_t)nc * 32 + slot];
        uint4 p3 = x16v[(size_t)nd * 32 + slot];
        if (slot == 0) {
            aw_out[na] = w0; aw_out[nb] = w1; aw_out[nc] = w2; aw_out[nd] = w3;
        }
        #pragma unroll
        for (int u = 0; u < 4; u++) {
            uint4 p = (u == 0) ? p0 : (u == 1) ? p1 : (u == 2) ? p2 : p3;
            float w = (u == 0) ? w0 : (u == 1) ? w1 : (u == 2) ? w2 : w3;
            float2 f0 = __half22float2(u32_as_h2(p.x));
            float2 f1 = __half22float2(u32_as_h2(p.y));
            float2 f2 = __half22float2(u32_as_h2(p.z));
            float2 f3 = __half22float2(u32_as_h2(p.w));
            acc[0] += w * f0.x; acc[1] += w * f0.y;
            acc[2] += w * f1.x; acc[3] += w * f1.y;
            acc[4] += w * f2.x; acc[5] += w * f2.y;
            acc[6] += w * f3.x; acc[7] += w * f3.y;
        }
    }
    for (; n < n_nodes; n += nstride) {
        float w = g_aw[n] * inv;
        uint4 p = x16v[(size_t)n * 32 + slot];
        if (slot == 0) aw_out[n] = w;
        float2 f0 = __half22float2(u32_as_h2(p.x));
        float2 f1 = __half22float2(u32_as_h2(p.y));
        float2 f2 = __half22float2(u32_as_h2(p.z));
        float2 f3 = __half22float2(u32_as_h2(p.w));
        acc[0] += w * f0.x; acc[1] += w * f0.y;
        acc[2] += w * f1.x; acc[3] += w * f1.y;
        acc[4] += w * f2.x; acc[5] += w * f2.y;
        acc[6] += w * f3.x; acc[7] += w * f3.y;
    }

    __shared__ float s_sh[IN_CH];
    if (threadIdx.x < IN_CH) s_sh[threadIdx.x] = 0.0f;
    __syncthreads();
    int cbase = slot * 8;
    #pragma unroll
    for (int j = 0; j < 8; j++)
        atomicAdd(&s_sh[cbase + j], acc[j]);
    __syncthreads();
    if (threadIdx.x < IN_CH) atomicAdd(&g_s[threadIdx.x], s_sh[threadIdx.x]);

    // ---- fused emb: ticketed last-32-blocks pattern ----
    __threadfence();
    __shared__ int ticket_s;
    if (threadIdx.x == 0) ticket_s = atomicAdd(&g_counter, 1);
    __syncthreads();
    int ticket = ticket_s;
    int nb_tot = gridDim.x;

    if (ticket >= nb_tot - EMB_BLOCKS) {
        if (threadIdx.x == 0) {
            while (*((volatile int*)&g_counter) < nb_tot) { }
        }
        __syncthreads();
        __threadfence();

        int role = ticket - (nb_tot - EMB_BLOCKS);     // 0..31
        int c    = threadIdx.x;                        // 0..255
        int i0   = role * (IN_CH / EMB_BLOCKS);        // 8 i-rows per block
        float acc2 = 0.0f;
        #pragma unroll
        for (int u = 0; u < IN_CH / EMB_BLOCKS; u++)
            acc2 += __ldcg(&g_s[i0 + u]) * __ldg(&Wv[(size_t)(i0 + u) * IN_CH + c]);
        if (role == 0) acc2 += bv[c];
        atomicAdd(&graph_emb[c], acc2);
    }
}

// ---------------------------------------------------------------------------
extern "C" void kernel_launch(void* const* d_in, const int* in_sizes, int n_in,
                              void* d_out, int out_size) {
    const float* x   = (const float*)d_in[0];
    const int*   ei  = (const int*)  d_in[1];
    const float* Wq  = (const float*)d_in[2];
    const float* bq  = (const float*)d_in[3];
    const float* Wk  = (const float*)d_in[4];
    const float* bk  = (const float*)d_in[5];
    const float* Wv  = (const float*)d_in[6];
    const float* bv  = (const float*)d_in[7];

    int n_nodes = in_sizes[0] / IN_CH;
    int n_edges = in_sizes[1] / 2;

    float* out = (float*)d_out;
    float* graph_emb = out;          // [256]
    float* aw_out    = out + IN_CH;  // [n_nodes]

    const int* row = ei;
    const int* col = ei + n_edges;

    qk_kernel<<<QK_GRID, 256>>>(x, Wq, bq, Wk, bk, graph_emb, n_nodes);
    edge_kernel<<<GRID6, 256>>>(row, col, Wv, bv, n_edges);
    pool_kernel<<<GRID6, 256>>>(Wv, bv, graph_emb, aw_out, n_nodes);
}

// round 16
// speedup vs baseline: 1.0303x; 1.0303x over previous
#include <cuda_runtime.h>

#define N_NODES_MAX 100000
#define IN_CH 256
#define QK_GRID 740            // 148 SMs * 5 blocks (regs ~48)
#define GRID6 888              // 148 SMs * 6 blocks
#define EMB_BLOCKS 32          // last 32 pool blocks do the final matvec
#define LOG2E 1.4426950408889634f

__device__ float g_q[N_NODES_MAX];
__device__ float g_k[N_NODES_MAX];   // stores k * log2(e)
__device__ float g_aw[N_NODES_MAX];
__device__ float g_sum;
__device__ float g_s[IN_CH];
__device__ int   g_counter;

// ---------------------------------------------------------------------------
// Kernel 1 (R8 winner): init + q[n] = x[n]·Wq + bq, k[n] = (x[n]·Wk+bk)·log2e.
// Warp per node, lane owns channels [8*lane, 8*lane+8), 4x node unroll.
// ---------------------------------------------------------------------------
__global__ void __launch_bounds__(256)
qk_kernel(const float* __restrict__ x,
          const float* __restrict__ Wq, const float* __restrict__ bq,
          const float* __restrict__ Wk, const float* __restrict__ bk,
          float* __restrict__ out,          // zero out[0:256] for emb atomics
          int n_nodes) {
    int tid     = blockIdx.x * blockDim.x + threadIdx.x;
    int nthread = gridDim.x * blockDim.x;

    if (tid < n_nodes) g_aw[tid] = 0.0f;
    if (tid < IN_CH)  { g_s[tid] = 0.0f; out[tid] = 0.0f; }
    if (tid == 0)     { g_sum = 0.0f; g_counter = 0; }

    int lane   = threadIdx.x & 31;
    int warp   = tid >> 5;
    int nwarps = nthread >> 5;

    const float4* wq4 = reinterpret_cast<const float4*>(Wq);
    const float4* wk4 = reinterpret_cast<const float4*>(Wk);
    float4 q0 = wq4[2 * lane], q1 = wq4[2 * lane + 1];
    float4 k0 = wk4[2 * lane], k1 = wk4[2 * lane + 1];
    float bqv = bq[0], bkv = bk[0];

    int n = warp;
    for (; n + 3 * nwarps < n_nodes; n += 4 * nwarps) {
        float dq[4], dk[4];
        #pragma unroll
        for (int u = 0; u < 4; u++) {
            const float4* xr = reinterpret_cast<const float4*>(
                x + (size_t)(n + u * nwarps) * IN_CH);
            float4 a = xr[2 * lane];
            float4 b = xr[2 * lane + 1];
            dq[u] = a.x*q0.x + a.y*q0.y + a.z*q0.z + a.w*q0.w
                  + b.x*q1.x + b.y*q1.y + b.z*q1.z + b.w*q1.w;
            dk[u] = a.x*k0.x + a.y*k0.y + a.z*k0.z + a.w*k0.w
                  + b.x*k1.x + b.y*k1.y + b.z*k1.z + b.w*k1.w;
        }
        #pragma unroll
        for (int o = 16; o > 0; o >>= 1) {
            #pragma unroll
            for (int u = 0; u < 4; u++) {
                dq[u] += __shfl_xor_sync(0xffffffffu, dq[u], o);
                dk[u] += __shfl_xor_sync(0xffffffffu, dk[u], o);
            }
        }
        if (lane == 0) {
            #pragma unroll
            for (int u = 0; u < 4; u++) {
                g_q[n + u * nwarps] = dq[u] + bqv;
                g_k[n + u * nwarps] = (dk[u] + bkv) * LOG2E;
            }
        }
    }
    for (; n < n_nodes; n += nwarps) {
        const float4* xr = reinterpret_cast<const float4*>(x + (size_t)n * IN_CH);
        float4 a = xr[2 * lane];
        float4 b = xr[2 * lane + 1];
        float dq = a.x*q0.x + a.y*q0.y + a.z*q0.z + a.w*q0.w
                 + b.x*q1.x + b.y*q1.y + b.z*q1.z + b.w*q1.w;
        float dk = a.x*k0.x + a.y*k0.y + a.z*k0.z + a.w*k0.w
                 + b.x*k1.x + b.y*k1.y + b.z*k1.z + b.w*k1.w;
        #pragma unroll
        for (int o = 16; o > 0; o >>= 1) {
            dq += __shfl_xor_sync(0xffffffffu, dq, o);
            dk += __shfl_xor_sync(0xffffffffu, dk, o);
        }
        if (lane == 0) { g_q[n] = dq + bqv; g_k[n] = (dk + bkv) * LOG2E; }
    }
}

// ---------------------------------------------------------------------------
// Kernel 2 (R8 winner, unchanged): edge pass, 8 edges/iter, in-loop sum.
// ---------------------------------------------------------------------------
__global__ void __launch_bounds__(256, 6)
edge_kernel(const int* __restrict__ row,
            const int* __restrict__ col,
            const float* __restrict__ Wv,
            const float* __restrict__ bv,
            int n_edges) {
    if (blockIdx.x < 64) {
        const float4* wv4 = reinterpret_cast<const float4*>(Wv);
        float4 p = __ldcg(&wv4[blockIdx.x * 256 + threadIdx.x]);
        float t = p.x + p.y + p.z + p.w;
        if (blockIdx.x == 0 && threadIdx.x < 64)
            t += __ldcg(&bv[threadIdx.x * 4]);
        if (t != t) atomicAdd(&g_sum, t);   // never true (no NaNs) — defeats DCE
    }

    int tid    = blockIdx.x * blockDim.x + threadIdx.x;
    int stride = gridDim.x * blockDim.x;
    int noct   = n_edges >> 3;

    const int4* row4 = reinterpret_cast<const int4*>(row);
    const int4* col4 = reinterpret_cast<const int4*>(col);

    float local = 0.0f;
    for (int i = tid; i < noct; i += stride) {
        int4 r0 = __ldcs(&row4[2 * i]), r1 = __ldcs(&row4[2 * i + 1]);
        int4 c0 = __ldcs(&col4[2 * i]), c1 = __ldcs(&col4[2 * i + 1]);

        float q0 = g_q[r0.x], q1 = g_q[r0.y], q2 = g_q[r0.z], q3 = g_q[r0.w];
        float q4 = g_q[r1.x], q5 = g_q[r1.y], q6 = g_q[r1.z], q7 = g_q[r1.w];
        float k0 = g_k[c0.x], k1 = g_k[c0.y], k2 = g_k[c0.z], k3 = g_k[c0.w];
        float k4 = g_k[c1.x], k5 = g_k[c1.y], k6 = g_k[c1.z], k7 = g_k[c1.w];

        float a0 = q0*k0, a1 = q1*k1, a2 = q2*k2, a3 = q3*k3;
        float a4 = q4*k4, a5 = q5*k5, a6 = q6*k6, a7 = q7*k7;
        a0 = fmaxf(a0, 0.2f*a0);  a1 = fmaxf(a1, 0.2f*a1);
        a2 = fmaxf(a2, 0.2f*a2);  a3 = fmaxf(a3, 0.2f*a3);
        a4 = fmaxf(a4, 0.2f*a4);  a5 = fmaxf(a5, 0.2f*a5);
        a6 = fmaxf(a6, 0.2f*a6);  a7 = fmaxf(a7, 0.2f*a7);
        float e0 = exp2f(a0), e1 = exp2f(a1), e2 = exp2f(a2), e3 = exp2f(a3);
        float e4 = exp2f(a4), e5 = exp2f(a5), e6 = exp2f(a6), e7 = exp2f(a7);

        atomicAdd(&g_aw[r0.x], e0);
        atomicAdd(&g_aw[r0.y], e1);
        atomicAdd(&g_aw[r0.z], e2);
        atomicAdd(&g_aw[r0.w], e3);
        atomicAdd(&g_aw[r1.x], e4);
        atomicAdd(&g_aw[r1.y], e5);
        atomicAdd(&g_aw[r1.z], e6);
        atomicAdd(&g_aw[r1.w], e7);
        local += ((e0 + e1) + (e2 + e3)) + ((e4 + e5) + (e6 + e7));
    }
    for (int e = (noct << 3) + tid; e < n_edges; e += stride) {
        float a = g_q[row[e]] * g_k[col[e]];
        a = fmaxf(a, 0.2f * a);
        float ex = exp2f(a);
        atomicAdd(&g_aw[row[e]], ex);
        local += ex;
    }

    __shared__ float sh[32];
    #pragma unroll
    for (int o = 16; o > 0; o >>= 1) local += __shfl_xor_sync(0xffffffffu, local, o);
    if ((threadIdx.x & 31) == 0) sh[threadIdx.x >> 5] = local;
    __syncthreads();
    if (threadIdx.x < 32) {
        float v = (threadIdx.x < (blockDim.x >> 5)) ? sh[threadIdx.x] : 0.0f;
        #pragma unroll
        for (int o = 16; o > 0; o >>= 1) v += __shfl_xor_sync(0xffffffffu, v, o);
        if (threadIdx.x == 0) atomicAdd(&g_sum, v);
    }
}

// ---------------------------------------------------------------------------
// Kernel 3 (restructured to qk's memory shape): warp-per-node, lane owns
// channels [8*lane, 8*lane+8) (two float4 loads per row), 4x node unroll
// -> 8 float4 loads in flight per lane (pool was 4 before: 52% DRAM).
// Then smem reduction + fused last-32-blocks emb.
// ---------------------------------------------------------------------------
__global__ void __launch_bounds__(256)
pool_kernel(const float* __restrict__ x,
            const float* __restrict__ Wv,
            const float* __restrict__ bv,
            float* __restrict__ graph_emb,
            float* __restrict__ aw_out,
            int n_nodes) {
    float inv = 1.0f / g_sum;
    int tid     = blockIdx.x * blockDim.x + threadIdx.x;
    int lane    = threadIdx.x & 31;
    int warp    = tid >> 5;
    int nwarps  = (gridDim.x * blockDim.x) >> 5;

    float acc[8];
    #pragma unroll
    for (int j = 0; j < 8; j++) acc[j] = 0.0f;

    int n = warp;
    for (; n + 3 * nwarps < n_nodes; n += 4 * nwarps) {
        #pragma unroll
        for (int u = 0; u < 4; u++) {
            int nu = n + u * nwarps;
            float w = g_aw[nu] * inv;               // warp-broadcast load
            const float4* xr = reinterpret_cast<const float4*>(
                x + (size_t)nu * IN_CH);
            float4 a = __ldcg(&xr[2 * lane]);
            float4 b = __ldcg(&xr[2 * lane + 1]);
            if (lane == 0) aw_out[nu] = w;
            acc[0] += w * a.x; acc[1] += w * a.y;
            acc[2] += w * a.z; acc[3] += w * a.w;
            acc[4] += w * b.x; acc[5] += w * b.y;
            acc[6] += w * b.z; acc[7] += w * b.w;
        }
    }
    for (; n < n_nodes; n += nwarps) {
        float w = g_aw[n] * inv;
        const float4* xr = reinterpret_cast<const float4*>(x + (size_t)n * IN_CH);
        float4 a = __ldcg(&xr[2 * lane]);
        float4 b = __ldcg(&xr[2 * lane + 1]);
        if (lane == 0) aw_out[n] = w;
        acc[0] += w * a.x; acc[1] += w * a.y;
        acc[2] += w * a.z; acc[3] += w * a.w;
        acc[4] += w * b.x; acc[5] += w * b.y;
        acc[6] += w * b.z; acc[7] += w * b.w;
    }

    __shared__ float s_sh[IN_CH];
    if (threadIdx.x < IN_CH) s_sh[threadIdx.x] = 0.0f;
    __syncthreads();
    int cbase = lane * 8;   // channels [8*lane, 8*lane+8)
    #pragma unroll
    for (int j = 0; j < 8; j++)
        atomicAdd(&s_sh[cbase + j], acc[j]);
    __syncthreads();
    if (threadIdx.x < IN_CH) atomicAdd(&g_s[threadIdx.x], s_sh[threadIdx.x]);

    // ---- fused emb: ticketed last-32-blocks pattern ----
    __threadfence();
    __shared__ int ticket_s;
    if (threadIdx.x == 0) ticket_s = atomicAdd(&g_counter, 1);
    __syncthreads();
    int ticket = ticket_s;
    int nb_tot = gridDim.x;

    if (ticket >= nb_tot - EMB_BLOCKS) {
        if (threadIdx.x == 0) {
            while (*((volatile int*)&g_counter) < nb_tot) { }
        }
        __syncthreads();
        __threadfence();

        int role = ticket - (nb_tot - EMB_BLOCKS);     // 0..31
        int c    = threadIdx.x;                        // 0..255
        int i0   = role * (IN_CH / EMB_BLOCKS);        // 8 i-rows per block
        float acc2 = 0.0f;
        #pragma unroll
        for (int u = 0; u < IN_CH / EMB_BLOCKS; u++)
            acc2 += __ldcg(&g_s[i0 + u]) * __ldg(&Wv[(size_t)(i0 + u) * IN_CH + c]);
        if (role == 0) acc2 += bv[c];
        atomicAdd(&graph_emb[c], acc2);
    }
}

// ---------------------------------------------------------------------------
extern "C" void kernel_launch(void* const* d_in, const int* in_sizes, int n_in,
                              void* d_out, int out_size) {
    const float* x   = (const float*)d_in[0];
    const int*   ei  = (const int*)  d_in[1];
    const float* Wq  = (const float*)d_in[2];
    const float* bq  = (const float*)d_in[3];
    const float* Wk  = (const float*)d_in[4];
    const float* bk  = (const float*)d_in[5];
    const float* Wv  = (const float*)d_in[6];
    const float* bv  = (const float*)d_in[7];

    int n_nodes = in_sizes[0] / IN_CH;
    int n_edges = in_sizes[1] / 2;

    float* out = (float*)d_out;
    float* graph_emb = out;          // [256]
    float* aw_out    = out + IN_CH;  // [n_nodes]

    const int* row = ei;
    const int* col = ei + n_edges;

    qk_kernel<<<QK_GRID, 256>>>(x, Wq, bq, Wk, bk, graph_emb, n_nodes);
    edge_kernel<<<GRID6, 256>>>(row, col, Wv, bv, n_edges);
    pool_kernel<<<QK_GRID, 256>>>(x, Wv, bv, graph_emb, aw_out, n_nodes);
}

// round 17
// speedup vs baseline: 1.0560x; 1.0249x over previous
#include <cuda_runtime.h>

#define N_NODES_MAX 100000
#define IN_CH 256
#define QK_GRID 740            // 148 SMs * 5 blocks (regs <=48)
#define GRID6 888              // 148 SMs * 6 blocks
#define EMB_BLOCKS 32          // last 32 pool blocks do the final matvec
#define LOG2E 1.4426950408889634f

__device__ float g_q[N_NODES_MAX];
__device__ float g_k[N_NODES_MAX];   // stores k * log2(e)
__device__ float g_aw[N_NODES_MAX];
__device__ float g_sum;
__device__ float g_s[IN_CH];
__device__ int   g_counter;

// ---------------------------------------------------------------------------
// Kernel 1 (R16 form, 20.2us measured): init + q/k projections.
// Warp per node, lane owns channels [8*lane, 8*lane+8), 4x node unroll.
// ---------------------------------------------------------------------------
__global__ void __launch_bounds__(256)
qk_kernel(const float* __restrict__ x,
          const float* __restrict__ Wq, const float* __restrict__ bq,
          const float* __restrict__ Wk, const float* __restrict__ bk,
          float* __restrict__ out,          // zero out[0:256] for emb atomics
          int n_nodes) {
    int tid     = blockIdx.x * blockDim.x + threadIdx.x;
    int nthread = gridDim.x * blockDim.x;

    if (tid < n_nodes) g_aw[tid] = 0.0f;
    if (tid < IN_CH)  { g_s[tid] = 0.0f; out[tid] = 0.0f; }
    if (tid == 0)     { g_sum = 0.0f; g_counter = 0; }

    int lane   = threadIdx.x & 31;
    int warp   = tid >> 5;
    int nwarps = nthread >> 5;

    const float4* wq4 = reinterpret_cast<const float4*>(Wq);
    const float4* wk4 = reinterpret_cast<const float4*>(Wk);
    float4 q0 = wq4[2 * lane], q1 = wq4[2 * lane + 1];
    float4 k0 = wk4[2 * lane], k1 = wk4[2 * lane + 1];
    float bqv = bq[0], bkv = bk[0];

    int n = warp;
    for (; n + 3 * nwarps < n_nodes; n += 4 * nwarps) {
        float dq[4], dk[4];
        #pragma unroll
        for (int u = 0; u < 4; u++) {
            const float4* xr = reinterpret_cast<const float4*>(
                x + (size_t)(n + u * nwarps) * IN_CH);
            float4 a = xr[2 * lane];
            float4 b = xr[2 * lane + 1];
            dq[u] = a.x*q0.x + a.y*q0.y + a.z*q0.z + a.w*q0.w
                  + b.x*q1.x + b.y*q1.y + b.z*q1.z + b.w*q1.w;
            dk[u] = a.x*k0.x + a.y*k0.y + a.z*k0.z + a.w*k0.w
                  + b.x*k1.x + b.y*k1.y + b.z*k1.z + b.w*k1.w;
        }
        #pragma unroll
        for (int o = 16; o > 0; o >>= 1) {
            #pragma unroll
            for (int u = 0; u < 4; u++) {
                dq[u] += __shfl_xor_sync(0xffffffffu, dq[u], o);
                dk[u] += __shfl_xor_sync(0xffffffffu, dk[u], o);
            }
        }
        if (lane == 0) {
            #pragma unroll
            for (int u = 0; u < 4; u++) {
                g_q[n + u * nwarps] = dq[u] + bqv;
                g_k[n + u * nwarps] = (dk[u] + bkv) * LOG2E;
            }
        }
    }
    for (; n < n_nodes; n += nwarps) {
        const float4* xr = reinterpret_cast<const float4*>(x + (size_t)n * IN_CH);
        float4 a = xr[2 * lane];
        float4 b = xr[2 * lane + 1];
        float dq = a.x*q0.x + a.y*q0.y + a.z*q0.z + a.w*q0.w
                 + b.x*q1.x + b.y*q1.y + b.z*q1.z + b.w*q1.w;
        float dk = a.x*k0.x + a.y*k0.y + a.z*k0.z + a.w*k0.w
                 + b.x*k1.x + b.y*k1.y + b.z*k1.z + b.w*k1.w;
        #pragma unroll
        for (int o = 16; o > 0; o >>= 1) {
            dq += __shfl_xor_sync(0xffffffffu, dq, o);
            dk += __shfl_xor_sync(0xffffffffu, dk, o);
        }
        if (lane == 0) { g_q[n] = dq + bqv; g_k[n] = (dk + bkv) * LOG2E; }
    }
}

// ---------------------------------------------------------------------------
// Kernel 2 (R8 winner, unchanged): edge pass, 8 edges/iter, in-loop sum.
// ---------------------------------------------------------------------------
__global__ void __launch_bounds__(256, 6)
edge_kernel(const int* __restrict__ row,
            const int* __restrict__ col,
            const float* __restrict__ Wv,
            const float* __restrict__ bv,
            int n_edges) {
    if (blockIdx.x < 64) {
        const float4* wv4 = reinterpret_cast<const float4*>(Wv);
        float4 p = __ldcg(&wv4[blockIdx.x * 256 + threadIdx.x]);
        float t = p.x + p.y + p.z + p.w;
        if (blockIdx.x == 0 && threadIdx.x < 64)
            t += __ldcg(&bv[threadIdx.x * 4]);
        if (t != t) atomicAdd(&g_sum, t);   // never true (no NaNs) — defeats DCE
    }

    int tid    = blockIdx.x * blockDim.x + threadIdx.x;
    int stride = gridDim.x * blockDim.x;
    int noct   = n_edges >> 3;

    const int4* row4 = reinterpret_cast<const int4*>(row);
    const int4* col4 = reinterpret_cast<const int4*>(col);

    float local = 0.0f;
    for (int i = tid; i < noct; i += stride) {
        int4 r0 = __ldcs(&row4[2 * i]), r1 = __ldcs(&row4[2 * i + 1]);
        int4 c0 = __ldcs(&col4[2 * i]), c1 = __ldcs(&col4[2 * i + 1]);

        float q0 = g_q[r0.x], q1 = g_q[r0.y], q2 = g_q[r0.z], q3 = g_q[r0.w];
        float q4 = g_q[r1.x], q5 = g_q[r1.y], q6 = g_q[r1.z], q7 = g_q[r1.w];
        float k0 = g_k[c0.x], k1 = g_k[c0.y], k2 = g_k[c0.z], k3 = g_k[c0.w];
        float k4 = g_k[c1.x], k5 = g_k[c1.y], k6 = g_k[c1.z], k7 = g_k[c1.w];

        float a0 = q0*k0, a1 = q1*k1, a2 = q2*k2, a3 = q3*k3;
        float a4 = q4*k4, a5 = q5*k5, a6 = q6*k6, a7 = q7*k7;
        a0 = fmaxf(a0, 0.2f*a0);  a1 = fmaxf(a1, 0.2f*a1);
        a2 = fmaxf(a2, 0.2f*a2);  a3 = fmaxf(a3, 0.2f*a3);
        a4 = fmaxf(a4, 0.2f*a4);  a5 = fmaxf(a5, 0.2f*a5);
        a6 = fmaxf(a6, 0.2f*a6);  a7 = fmaxf(a7, 0.2f*a7);
        float e0 = exp2f(a0), e1 = exp2f(a1), e2 = exp2f(a2), e3 = exp2f(a3);
        float e4 = exp2f(a4), e5 = exp2f(a5), e6 = exp2f(a6), e7 = exp2f(a7);

        atomicAdd(&g_aw[r0.x], e0);
        atomicAdd(&g_aw[r0.y], e1);
        atomicAdd(&g_aw[r0.z], e2);
        atomicAdd(&g_aw[r0.w], e3);
        atomicAdd(&g_aw[r1.x], e4);
        atomicAdd(&g_aw[r1.y], e5);
        atomicAdd(&g_aw[r1.z], e6);
        atomicAdd(&g_aw[r1.w], e7);
        local += ((e0 + e1) + (e2 + e3)) + ((e4 + e5) + (e6 + e7));
    }
    for (int e = (noct << 3) + tid; e < n_edges; e += stride) {
        float a = g_q[row[e]] * g_k[col[e]];
        a = fmaxf(a, 0.2f * a);
        float ex = exp2f(a);
        atomicAdd(&g_aw[row[e]], ex);
        local += ex;
    }

    __shared__ float sh[32];
    #pragma unroll
    for (int o = 16; o > 0; o >>= 1) local += __shfl_xor_sync(0xffffffffu, local, o);
    if ((threadIdx.x & 31) == 0) sh[threadIdx.x >> 5] = local;
    __syncthreads();
    if (threadIdx.x < 32) {
        float v = (threadIdx.x < (blockDim.x >> 5)) ? sh[threadIdx.x] : 0.0f;
        #pragma unroll
        for (int o = 16; o > 0; o >>= 1) v += __shfl_xor_sync(0xffffffffu, v, o);
        if (threadIdx.x == 0) atomicAdd(&g_sum, v);
    }
}

// ---------------------------------------------------------------------------
// Kernel 3: warp-per-node pool (qk's memory shape) with FIXED occupancy:
// __launch_bounds__(256,5) forces <=48 regs -> 5 blocks/SM -> grid 740 is
// one balanced wave (R16 regression was a reg/occupancy bug, not the shape).
// ---------------------------------------------------------------------------
__global__ void __launch_bounds__(256, 5)
pool_kernel(const float* __restrict__ x,
            const float* __restrict__ Wv,
            const float* __restrict__ bv,
            float* __restrict__ graph_emb,
            float* __restrict__ aw_out,
            int n_nodes) {
    float inv = 1.0f / g_sum;
    int tid     = blockIdx.x * blockDim.x + threadIdx.x;
    int lane    = threadIdx.x & 31;
    int warp    = tid >> 5;
    int nwarps  = (gridDim.x * blockDim.x) >> 5;

    float acc[8];
    #pragma unroll
    for (int j = 0; j < 8; j++) acc[j] = 0.0f;

    int n = warp;
    for (; n + 3 * nwarps < n_nodes; n += 4 * nwarps) {
        #pragma unroll
        for (int u = 0; u < 4; u++) {
            int nu = n + u * nwarps;
            float w = g_aw[nu] * inv;               // warp-broadcast load
            const float4* xr = reinterpret_cast<const float4*>(
                x + (size_t)nu * IN_CH);
            float4 a = __ldcg(&xr[2 * lane]);
            float4 b = __ldcg(&xr[2 * lane + 1]);
            if (lane == 0) aw_out[nu] = w;
            acc[0] += w * a.x; acc[1] += w * a.y;
            acc[2] += w * a.z; acc[3] += w * a.w;
            acc[4] += w * b.x; acc[5] += w * b.y;
            acc[6] += w * b.z; acc[7] += w * b.w;
        }
    }
    for (; n < n_nodes; n += nwarps) {
        float w = g_aw[n] * inv;
        const float4* xr = reinterpret_cast<const float4*>(x + (size_t)n * IN_CH);
        float4 a = __ldcg(&xr[2 * lane]);
        float4 b = __ldcg(&xr[2 * lane + 1]);
        if (lane == 0) aw_out[n] = w;
        acc[0] += w * a.x; acc[1] += w * a.y;
        acc[2] += w * a.z; acc[3] += w * a.w;
        acc[4] += w * b.x; acc[5] += w * b.y;
        acc[6] += w * b.z; acc[7] += w * b.w;
    }

    __shared__ float s_sh[IN_CH];
    if (threadIdx.x < IN_CH) s_sh[threadIdx.x] = 0.0f;
    __syncthreads();
    int cbase = lane * 8;   // channels [8*lane, 8*lane+8)
    #pragma unroll
    for (int j = 0; j < 8; j++)
        atomicAdd(&s_sh[cbase + j], acc[j]);
    __syncthreads();
    if (threadIdx.x < IN_CH) atomicAdd(&g_s[threadIdx.x], s_sh[threadIdx.x]);

    // ---- fused emb: ticketed last-32-blocks pattern ----
    __threadfence();
    __shared__ int ticket_s;
    if (threadIdx.x == 0) ticket_s = atomicAdd(&g_counter, 1);
    __syncthreads();
    int ticket = ticket_s;
    int nb_tot = gridDim.x;

    if (ticket >= nb_tot - EMB_BLOCKS) {
        if (threadIdx.x == 0) {
            while (*((volatile int*)&g_counter) < nb_tot) { }
        }
        __syncthreads();
        __threadfence();

        int role = ticket - (nb_tot - EMB_BLOCKS);     // 0..31
        int c    = threadIdx.x;                        // 0..255
        int i0   = role * (IN_CH / EMB_BLOCKS);        // 8 i-rows per block
        float acc2 = 0.0f;
        #pragma unroll
        for (int u = 0; u < IN_CH / EMB_BLOCKS; u++)
            acc2 += __ldcg(&g_s[i0 + u]) * __ldg(&Wv[(size_t)(i0 + u) * IN_CH + c]);
        if (role == 0) acc2 += bv[c];
        atomicAdd(&graph_emb[c], acc2);
    }
}

// ---------------------------------------------------------------------------
extern "C" void kernel_launch(void* const* d_in, const int* in_sizes, int n_in,
                              void* d_out, int out_size) {
    const float* x   = (const float*)d_in[0];
    const int*   ei  = (const int*)  d_in[1];
    const float* Wq  = (const float*)d_in[2];
    const float* bq  = (const float*)d_in[3];
    const float* Wk  = (const float*)d_in[4];
    const float* bk  = (const float*)d_in[5];
    const float* Wv  = (const float*)d_in[6];
    const float* bv  = (const float*)d_in[7];

    int n_nodes = in_sizes[0] / IN_CH;
    int n_edges = in_sizes[1] / 2;

    float* out = (float*)d_out;
    float* graph_emb = out;          // [256]
    float* aw_out    = out + IN_CH;  // [n_nodes]

    const int* row = ei;
    const int* col = ei + n_edges;

    qk_kernel<<<QK_GRID, 256>>>(x, Wq, bq, Wk, bk, graph_emb, n_nodes);
    edge_kernel<<<GRID6, 256>>>(row, col, Wv, bv, n_edges);
    pool_kernel<<<QK_GRID, 256>>>(x, Wv, bv, graph_emb, aw_out, n_nodes);
}